// round 15
// baseline (speedup 1.0000x reference)
#include <cuda_runtime.h>
#include <math_constants.h>

#define NTOK 1024
#define DIM 128
#define TI 8            // rows per block (attn)
#define TJ 64           // j-tile
#define NT 1024         // threads, attn (32 warps)
#define KP 132          // K/V smem pitch
#define NTILE (NTOK / TJ)
#define LOG2E 1.4426950408889634f

typedef unsigned long long ull;

// packed f32x2 helpers (sm_100+/sm_103a)
__device__ __forceinline__ ull ADD2(ull a, ull b) {
    ull r; asm("add.rn.f32x2 %0, %1, %2;" : "=l"(r) : "l"(a), "l"(b)); return r;
}
__device__ __forceinline__ ull FMA2(ull a, ull b, ull c) {
    ull r; asm("fma.rn.f32x2 %0, %1, %2, %3;" : "=l"(r) : "l"(a), "l"(b), "l"(c)); return r;
}
// packed relu via scalar FMNMX pair (no packed f32 max; FMNMX = alu pipe)
__device__ __forceinline__ ull RELU2(ull a) {
    float lo, hi;
    asm("mov.b64 {%0, %1}, %2;" : "=f"(lo), "=f"(hi) : "l"(a));
    lo = fmaxf(lo, 0.f); hi = fmaxf(hi, 0.f);
    ull r; asm("mov.b64 %0, {%1, %2};" : "=l"(r) : "f"(lo), "f"(hi)); return r;
}
__device__ __forceinline__ float HSUM2(ull a) {
    float lo, hi;
    asm("mov.b64 {%0, %1}, %2;" : "=f"(lo), "=f"(hi) : "l"(a));
    return lo + hi;
}
// cp.async 16B
__device__ __forceinline__ void cpa16(unsigned dst, const void* src) {
    asm volatile("cp.async.cg.shared.global [%0], [%1], 16;" :: "r"(dst), "l"(src));
}
#define CP_COMMIT() asm volatile("cp.async.commit_group;" ::: "memory")
#define CP_WAIT0()  asm volatile("cp.async.wait_group 0;" ::: "memory")

// scratch for Q,K,V (static device arrays — no allocation)
__device__ float g_Q[NTOK * DIM];
__device__ float g_K[NTOK * DIM];
__device__ float g_V[NTOK * DIM];

// ---------------------------------------------------------------------------
// Kernel 1: Q,K,V = x @ W + b.  128 blocks x 384 threads.
// ---------------------------------------------------------------------------
__global__ __launch_bounds__(384) void qkv_kernel(
    const float* __restrict__ x,
    const float* __restrict__ WQ, const float* __restrict__ bQ,
    const float* __restrict__ WK, const float* __restrict__ bK,
    const float* __restrict__ WV, const float* __restrict__ bV)
{
    __shared__ float xs[8 * DIM];
    const int tid = threadIdx.x;
    const int i0 = blockIdx.x * 8;

    for (int idx = tid; idx < 8 * DIM; idx += 384)
        xs[idx] = x[i0 * DIM + idx];
    __syncthreads();

    const int d   = tid & 127;
    const int mat = tid >> 7;   // 0=Q 1=K 2=V
    const float* W = (mat == 0) ? WQ : (mat == 1) ? WK : WV;
    const float* b = (mat == 0) ? bQ : (mat == 1) ? bK : bV;
    float* outp    = (mat == 0) ? g_Q : (mat == 1) ? g_K : g_V;

    float acc[8];
    const float bv = b[d];
#pragma unroll
    for (int r = 0; r < 8; r++) acc[r] = bv;

#pragma unroll 4
    for (int k = 0; k < DIM; k += 4) {
        const float w0 = W[(k + 0) * DIM + d];
        const float w1 = W[(k + 1) * DIM + d];
        const float w2 = W[(k + 2) * DIM + d];
        const float w3 = W[(k + 3) * DIM + d];
#pragma unroll
        for (int r = 0; r < 8; r++) {
            const float4 xq = *(const float4*)&xs[r * DIM + k];
            acc[r] = fmaf(xq.x, w0, fmaf(xq.y, w1, fmaf(xq.z, w2, fmaf(xq.w, w3, acc[r]))));
        }
    }
#pragma unroll
    for (int r = 0; r < 8; r++)
        outp[(i0 + r) * DIM + d] = acc[r];
}

// ---------------------------------------------------------------------------
// Kernel 2: fused pass, TI=8, 1024 threads (32 warps = 8/SMSP), 1 CTA/SM,
// grid 128. K,V double-buffered cp.async, 2 barriers/tile, ~64 regs/thread.
//   phase-e: warp w: rh_e=w>>4, je=(w&15)*4+(lane&3), g=lane>>2 in [0,8);
//            4 E_ITs over 1/8 of d; 3-round shfl reduce-scatter -> lanes<16
//            own row (rh_e*4 + (g&3)) at column je; 1 exp2; p duplicated.
//   accumulate: thread (dp=tid&63, jq=(tid>>6)&3, rg=tid>>8): rows 2rg,2rg+1,
//            16 j; 4 packed accumulators; one LDS.128 p per j.
// smem ~144KB.
// ---------------------------------------------------------------------------
__global__ __launch_bounds__(NT, 1) void attn_kernel(
    const float* __restrict__ wA,
    const float* __restrict__ W_Ev,
    const float* __restrict__ b_Ev,
    float* __restrict__ out)
{
    extern __shared__ float sm[];
    float* Kb0  = sm;              // [TJ][KP] = 8448
    float* Kb1  = sm + 8448;
    float* Vb0  = sm + 16896;
    float* Vb1  = sm + 25344;
    float* Qe   = sm + 33792;      // [8][DIM] = 1024
    float* wAs  = sm + 34816;      // [DIM] = 128
    float* p16d = sm + 34944;      // [TJ][16] duplicated p = 1024
    float* l_ws = sm + 35968;      // [32][4] = 128
    // total 36096 floats = 144384 B

    const int tid  = threadIdx.x;
    const int lane = tid & 31;
    const int warp = tid >> 5;
    const int i0   = blockIdx.x * TI;
    // phase-e ids
    const int rh_e = warp >> 4;               // row half 0/1
    const int je   = ((warp & 15) << 2) + (lane & 3);
    const int g    = lane >> 2;               // d-chunk in [0,8)
    // accumulate ids
    const int dp   = tid & 63;                // d-pair
    const int jq   = (tid >> 6) & 3;          // j-quarter
    const int rg   = tid >> 8;                // row-pair group in [0,4)

    // per-thread tile slots: float4 idx = it*NT + tid (2 slots)
    unsigned koff[2];
#pragma unroll
    for (int it = 0; it < 2; it++) {
        const int idx = it * NT + tid;
        koff[it] = (unsigned)(((idx >> 5) * KP + (idx & 31) * 4) * 4);
    }
    const unsigned kb0 = (unsigned)__cvta_generic_to_shared(Kb0);
    const unsigned kb1 = (unsigned)__cvta_generic_to_shared(Kb1);
    const unsigned vb0 = (unsigned)__cvta_generic_to_shared(Vb0);
    const unsigned vb1 = (unsigned)__cvta_generic_to_shared(Vb1);

    // init Q table (row-major, 8 rows) + wA
    if (tid < TI * DIM) {
        const int r = tid >> 7, dd = tid & 127;
        Qe[tid] = g_Q[(i0 + r) * DIM + dd];
    }
    if (tid < DIM) wAs[tid] = wA[tid];

    // accumulate-phase Q d-pairs (rows 2rg, 2rg+1)
    const ull q0p = *(const ull*)&g_Q[(i0 + 2 * rg + 0) * DIM + 2 * dp];
    const ull q1p = *(const ull*)&g_Q[(i0 + 2 * rg + 1) * DIM + 2 * dp];

    ull af0 = 0ull, af1 = 0ull;
    ull av0 = 0ull, av1 = 0ull;
    float l_acc = 0.f;

    // prologue: async-load K(0), V(0) into buf0
    {
        const float4* Kg = (const float4*)(g_K);
        const float4* Vg = (const float4*)(g_V);
#pragma unroll
        for (int it = 0; it < 2; it++) {
            cpa16(kb0 + koff[it], &Kg[it * NT + tid]);
            cpa16(vb0 + koff[it], &Vg[it * NT + tid]);
        }
        CP_COMMIT();
    }

    for (int ti = 0; ti < NTILE; ti++) {
        const float* Kcur = (ti & 1) ? Kb1 : Kb0;
        const float* Vcur = (ti & 1) ? Vb1 : Vb0;

        CP_WAIT0();        // K(ti), V(ti) landed
        __syncthreads();   // visible; prev accumulate done (covers Qe/wAs ti=0)

        // ---- phase e/p: e over d-chunk g for 4 rows (half rh_e) at column je
        {
            ull e0 = 0ull, e1 = 0ull, e2 = 0ull, e3 = 0ull;
            const float* kpE = Kcur + je * KP;
            const float* QhE = Qe + rh_e * 4 * DIM;
#pragma unroll
            for (int it = 0; it < 4; it++) {
                const int b = (g + it * 8) * 4;   // float offset of 4-d block
                const ulonglong2 k2 = *(const ulonglong2*)&kpE[b];
                const ulonglong2 w2 = *(const ulonglong2*)&wAs[b];
                {
                    const ulonglong2 q2 = *(const ulonglong2*)&QhE[0 * DIM + b];
                    e0 = FMA2(RELU2(ADD2(q2.x, k2.x)), w2.x, e0);
                    e0 = FMA2(RELU2(ADD2(q2.y, k2.y)), w2.y, e0);
                }
                {
                    const ulonglong2 q2 = *(const ulonglong2*)&QhE[1 * DIM + b];
                    e1 = FMA2(RELU2(ADD2(q2.x, k2.x)), w2.x, e1);
                    e1 = FMA2(RELU2(ADD2(q2.y, k2.y)), w2.y, e1);
                }
                {
                    const ulonglong2 q2 = *(const ulonglong2*)&QhE[2 * DIM + b];
                    e2 = FMA2(RELU2(ADD2(q2.x, k2.x)), w2.x, e2);
                    e2 = FMA2(RELU2(ADD2(q2.y, k2.y)), w2.y, e2);
                }
                {
                    const ulonglong2 q2 = *(const ulonglong2*)&QhE[3 * DIM + b];
                    e3 = FMA2(RELU2(ADD2(q2.x, k2.x)), w2.x, e3);
                    e3 = FMA2(RELU2(ADD2(q2.y, k2.y)), w2.y, e3);
                }
            }
            float f0 = HSUM2(e0), f1 = HSUM2(e1), f2 = HSUM2(e2), f3 = HSUM2(e3);
            // reduce-scatter over g (3 shfl rounds: xor4, xor8, xor16)
            const bool hi0 = (g & 1);
            float sA = hi0 ? f0 : f1;
            float sB = hi0 ? f2 : f3;
            const float rA = __shfl_xor_sync(0xffffffffu, sA, 4);
            const float rB = __shfl_xor_sync(0xffffffffu, sB, 4);
            const float u_ = (hi0 ? f1 : f0) + rA;   // row (g&1)
            const float v_ = (hi0 ? f3 : f2) + rB;   // row 2+(g&1)
            const bool hi1 = ((g >> 1) & 1);
            float s2 = hi1 ? u_ : v_;
            const float r2 = __shfl_xor_sync(0xffffffffu, s2, 8);
            const float ep = (hi1 ? v_ : u_) + r2;   // row g&3, partial over g bit2
            const float e_ = ep + __shfl_xor_sync(0xffffffffu, ep, 16);  // full
            const float p_ = exp2f(e_ * LOG2E);      // |e| <~ 3: no max-shift
            if (lane < 16) {   // lanes 16..31 duplicate
                *(float2*)&p16d[je * 16 + 2 * (rh_e * 4 + (g & 3))]
                    = make_float2(p_, p_);
                l_acc += p_;
            }
        }
        __syncthreads();   // p16d ready; phase-e reads of Kcur done

        // issue K(ti+1), V(ti+1) into other buffers — overlaps accumulate
        if (ti + 1 < NTILE) {
            const unsigned kbn = (ti & 1) ? kb0 : kb1;
            const unsigned vbn = (ti & 1) ? vb0 : vb1;
            const float4* Kg = (const float4*)(g_K + (ti + 1) * TJ * DIM);
            const float4* Vg = (const float4*)(g_V + (ti + 1) * TJ * DIM);
#pragma unroll
            for (int it = 0; it < 2; it++) {
                cpa16(kbn + koff[it], &Kg[it * NT + tid]);
                cpa16(vbn + koff[it], &Vg[it * NT + tid]);
            }
            CP_COMMIT();
        }

        // ---- accumulate: d-pair dp, rows 2rg/2rg+1, j-quarter jq
        {
            const float* kpb = Kcur + 2 * dp;
            const float* vpb = Vcur + 2 * dp;
            const float* pp  = p16d + 4 * rg;
#pragma unroll 4
            for (int jj = 0; jj < 16; jj++) {
                const int j = jq * 16 + jj;
                const ull kv = *(const ull*)&kpb[j * KP];
                const ull vv = *(const ull*)&vpb[j * KP];
                const ulonglong2 pq = *(const ulonglong2*)&pp[j * 16]; // {p2rg,p2rg},{p2rg+1,p2rg+1}
                af0 = FMA2(pq.x, RELU2(ADD2(q0p, kv)), af0);
                av0 = FMA2(pq.x, vv, av0);
                af1 = FMA2(pq.y, RELU2(ADD2(q1p, kv)), af1);
                av1 = FMA2(pq.y, vv, av1);
            }
        }
    }

    // ================= epilogue =================
    // reduce l_acc over the 4 je-lanes of each g-quad (lanes<16 hold values)
    l_acc += __shfl_xor_sync(0xffffffffu, l_acc, 1);
    l_acc += __shfl_xor_sync(0xffffffffu, l_acc, 2);
    if (lane < 16 && (lane & 3) == 0)
        l_ws[warp * 4 + (lane >> 2)] = l_acc;   // row (rh_e*4 + g), g=lane>>2<4
    __syncthreads();                 // main-loop reads done; l_ws published

    // exchange: xch[a][rg][jq][dp] as ull (a: 0=af0,1=af1,2=av0,3=av1) in Kb0
    ull* xch = (ull*)Kb0;            // 4*4*4*64 = 4096 ull = 32KB <= 33KB
    {
        const int bse = (rg * 4 + jq) * 64 + dp;
        xch[bse + 0 * 1024] = af0;
        xch[bse + 1 * 1024] = af1;
        xch[bse + 2 * 1024] = av0;
        xch[bse + 3 * 1024] = av1;
    }
    __syncthreads();

    // combine over jq, normalize; Rp[k][8] in Vb1, avs[8][128] in Qe
    float* Rp  = Vb1;
    float* avs = Qe;
    {
        const int d = tid & 127, r = tid >> 7;   // one (d, r) per thread
        const int dpc = d >> 1, hc = d & 1;
        const int rgg = r >> 1, sub = r & 1;
        const int rhh = r >> 2, ra = r & 3;
        const float* xf = (const float*)xch;
        float lr = 0.f;
#pragma unroll
        for (int w = 0; w < 16; w++) lr += l_ws[(rhh * 16 + w) * 4 + ra];
        const float il = 1.f / lr;
        float af = 0.f, av = 0.f;
#pragma unroll
        for (int q = 0; q < 4; q++) {
            af += xf[(((sub    ) * 1024 + (rgg * 4 + q) * 64 + dpc)) * 2 + hc];
            av += xf[(((2 + sub) * 1024 + (rgg * 4 + q) * 64 + dpc)) * 2 + hc];
        }
        Rp[d * 8 + r]    = af * il;
        avs[r * 128 + d] = av * il;
    }
    __syncthreads();

    // GEMM: thread (d, r) computes out[i0+r][d]
    {
        const int d = tid & 127, r = tid >> 7;
        float o = avs[r * 128 + d] + b_Ev[d];
#pragma unroll 8
        for (int k = 0; k < DIM; k++) {
            o += W_Ev[k * DIM + d] * Rp[k * 8 + r];   // LDG coalesced + LDS bcast
        }
        out[(i0 + r) * DIM + d] = o;
    }
}

// ---------------------------------------------------------------------------
extern "C" void kernel_launch(void* const* d_in, const int* in_sizes, int n_in,
                              void* d_out, int out_size)
{
    const float* x    = (const float*)d_in[0];
    const float* W_Q  = (const float*)d_in[1];
    const float* b_Q  = (const float*)d_in[2];
    const float* W_K  = (const float*)d_in[3];
    const float* b_K  = (const float*)d_in[4];
    const float* W_V  = (const float*)d_in[5];
    const float* b_V  = (const float*)d_in[6];
    const float* W_Ev = (const float*)d_in[7];
    const float* b_Ev = (const float*)d_in[8];
    const float* W_A  = (const float*)d_in[9];
    // d_in[10] = b_A: cancels in softmax; sum(alpha)=1 handles b_Ev; unused.
    float* out = (float*)d_out;

    const int smem2 = 36096 * (int)sizeof(float);  // 144384 B -> 1 CTA/SM
    cudaFuncSetAttribute(attn_kernel, cudaFuncAttributeMaxDynamicSharedMemorySize, smem2);

    qkv_kernel<<<NTOK / 8, 384>>>(x, W_Q, b_Q, W_K, b_K, W_V, b_V);
    attn_kernel<<<NTOK / TI, NT, smem2>>>(W_A, W_Ev, b_Ev, out);
}

// round 16
// speedup vs baseline: 1.1131x; 1.1131x over previous
#include <cuda_runtime.h>
#include <math_constants.h>

#define NTOK 1024
#define DIM 128
#define TI 8            // rows per block (attn)
#define TJ 64           // j-tile
#define NT 512          // threads, attn
#define KP2 260         // interleaved KV smem pitch (floats): 64 tokens x 256 + pad
#define NTILE (NTOK / TJ)
#define LOG2E 1.4426950408889634f

typedef unsigned long long ull;

// packed f32x2 helpers (sm_100+/sm_103a)
__device__ __forceinline__ ull ADD2(ull a, ull b) {
    ull r; asm("add.rn.f32x2 %0, %1, %2;" : "=l"(r) : "l"(a), "l"(b)); return r;
}
__device__ __forceinline__ ull FMA2(ull a, ull b, ull c) {
    ull r; asm("fma.rn.f32x2 %0, %1, %2, %3;" : "=l"(r) : "l"(a), "l"(b), "l"(c)); return r;
}
// packed relu via scalar FMNMX pair (no packed f32 max; FMNMX = alu pipe)
__device__ __forceinline__ ull RELU2(ull a) {
    float lo, hi;
    asm("mov.b64 {%0, %1}, %2;" : "=f"(lo), "=f"(hi) : "l"(a));
    lo = fmaxf(lo, 0.f); hi = fmaxf(hi, 0.f);
    ull r; asm("mov.b64 %0, {%1, %2};" : "=l"(r) : "f"(lo), "f"(hi)); return r;
}
__device__ __forceinline__ float HSUM2(ull a) {
    float lo, hi;
    asm("mov.b64 {%0, %1}, %2;" : "=f"(lo), "=f"(hi) : "l"(a));
    return lo + hi;
}
// cp.async 16B
__device__ __forceinline__ void cpa16(unsigned dst, const void* src) {
    asm volatile("cp.async.cg.shared.global [%0], [%1], 16;" :: "r"(dst), "l"(src));
}
#define CP_COMMIT() asm volatile("cp.async.commit_group;" ::: "memory")
#define CP_WAIT0()  asm volatile("cp.async.wait_group 0;" ::: "memory")

// scratch (static device arrays — no allocation)
__device__ float g_Q[NTOK * DIM];
__device__ float g_KV[NTOK * DIM * 2];   // interleaved: token*256 + dp*4 + {k0,k1,v0,v1}

// ---------------------------------------------------------------------------
// Kernel 1: Q,K,V = x @ W + b.  128 blocks x 384 threads.
// K,V written interleaved into g_KV.
// ---------------------------------------------------------------------------
__global__ __launch_bounds__(384) void qkv_kernel(
    const float* __restrict__ x,
    const float* __restrict__ WQ, const float* __restrict__ bQ,
    const float* __restrict__ WK, const float* __restrict__ bK,
    const float* __restrict__ WV, const float* __restrict__ bV)
{
    __shared__ float xs[8 * DIM];
    const int tid = threadIdx.x;
    const int i0 = blockIdx.x * 8;

    for (int idx = tid; idx < 8 * DIM; idx += 384)
        xs[idx] = x[i0 * DIM + idx];
    __syncthreads();

    const int d   = tid & 127;
    const int mat = tid >> 7;   // 0=Q 1=K 2=V
    const float* W = (mat == 0) ? WQ : (mat == 1) ? WK : WV;
    const float* b = (mat == 0) ? bQ : (mat == 1) ? bK : bV;

    float acc[8];
    const float bv = b[d];
#pragma unroll
    for (int r = 0; r < 8; r++) acc[r] = bv;

#pragma unroll 4
    for (int k = 0; k < DIM; k += 4) {
        const float w0 = W[(k + 0) * DIM + d];
        const float w1 = W[(k + 1) * DIM + d];
        const float w2 = W[(k + 2) * DIM + d];
        const float w3 = W[(k + 3) * DIM + d];
#pragma unroll
        for (int r = 0; r < 8; r++) {
            const float4 xq = *(const float4*)&xs[r * DIM + k];
            acc[r] = fmaf(xq.x, w0, fmaf(xq.y, w1, fmaf(xq.z, w2, fmaf(xq.w, w3, acc[r]))));
        }
    }
    if (mat == 0) {
#pragma unroll
        for (int r = 0; r < 8; r++)
            g_Q[(i0 + r) * DIM + d] = acc[r];
    } else {
        const int base = (d >> 1) * 4 + (d & 1) + ((mat == 2) ? 2 : 0);
#pragma unroll
        for (int r = 0; r < 8; r++)
            g_KV[(i0 + r) * 256 + base] = acc[r];
    }
}

// ---- phase bodies as macros (straight-line, interleavable) -----------------
#define E_IT(it) { \
    const int w_ = (g + (it) * 4) * 4; \
    const int b_ = w_ * 2; \
    const ull kx = *(const ull*)&kpE[b_]; \
    const ull ky = *(const ull*)&kpE[b_ + 4]; \
    const ulonglong2 w2 = *(const ulonglong2*)&wAs[w_]; \
    { const ulonglong2 q2 = *(const ulonglong2*)&QhE[0 * DIM + w_]; \
      e0 = FMA2(RELU2(ADD2(q2.x, kx)), w2.x, e0); \
      e0 = FMA2(RELU2(ADD2(q2.y, ky)), w2.y, e0); } \
    { const ulonglong2 q2 = *(const ulonglong2*)&QhE[1 * DIM + w_]; \
      e1 = FMA2(RELU2(ADD2(q2.x, kx)), w2.x, e1); \
      e1 = FMA2(RELU2(ADD2(q2.y, ky)), w2.y, e1); } \
    { const ulonglong2 q2 = *(const ulonglong2*)&QhE[2 * DIM + w_]; \
      e2 = FMA2(RELU2(ADD2(q2.x, kx)), w2.x, e2); \
      e2 = FMA2(RELU2(ADD2(q2.y, ky)), w2.y, e2); } \
    { const ulonglong2 q2 = *(const ulonglong2*)&QhE[3 * DIM + w_]; \
      e3 = FMA2(RELU2(ADD2(q2.x, kx)), w2.x, e3); \
      e3 = FMA2(RELU2(ADD2(q2.y, ky)), w2.y, e3); } }

#define E_FIN() { \
    float f0 = HSUM2(e0), f1 = HSUM2(e1), f2 = HSUM2(e2), f3 = HSUM2(e3); \
    const bool hi0 = (g & 1); \
    float sA = hi0 ? f0 : f1; \
    float sB = hi0 ? f2 : f3; \
    const float rA = __shfl_xor_sync(0xffffffffu, sA, 8); \
    const float rB = __shfl_xor_sync(0xffffffffu, sB, 8); \
    const float u_ = (hi0 ? f1 : f0) + rA; \
    const float v_ = (hi0 ? f3 : f2) + rB; \
    const bool hi1 = (g >> 1); \
    float s2 = hi1 ? u_ : v_; \
    const float r2 = __shfl_xor_sync(0xffffffffu, s2, 16); \
    const float e_ = (hi1 ? v_ : u_) + r2; \
    const float p_ = exp2f(e_ * LOG2E); \
    *(float2*)&p_cur[je * 16 + 2 * (rh_e * 4 + g)] = make_float2(p_, p_); \
    l_acc += p_; }

#define ACC_J(jj) { \
    const int j_ = jq * 16 + (jj); \
    const ulonglong2 kvv = *(const ulonglong2*)&kvpA[j_ * KP2]; \
    const ulonglong2 pA = *(const ulonglong2*)&ppA[j_ * 16]; \
    const ulonglong2 pB = *(const ulonglong2*)&ppA[j_ * 16 + 4]; \
    af0 = FMA2(pA.x, RELU2(ADD2(q0p, kvv.x)), af0); av0 = FMA2(pA.x, kvv.y, av0); \
    af1 = FMA2(pA.y, RELU2(ADD2(q1p, kvv.x)), af1); av1 = FMA2(pA.y, kvv.y, av1); \
    af2 = FMA2(pB.x, RELU2(ADD2(q2p, kvv.x)), af2); av2 = FMA2(pB.x, kvv.y, av2); \
    af3 = FMA2(pB.y, RELU2(ADD2(q3p, kvv.x)), af3); av3 = FMA2(pB.y, kvv.y, av3); }

// ---------------------------------------------------------------------------
// Kernel 2: fused pass, TI=8, 512 threads, 1 CTA/SM, intra-thread pipeline:
//   merged phase-e(ti)+accumulate(ti-1); KV interleaved tile, triple-buffered
//   cp.async; ONE __syncthreads per tile. Accumulate: 1 LDS.128 per j fetches
//   the thread's K-pair AND V-pair together.
// smem 212.7 KB.
// ---------------------------------------------------------------------------
__global__ __launch_bounds__(NT, 1) void attn_kernel(
    const float* __restrict__ wA,
    const float* __restrict__ W_Ev,
    const float* __restrict__ b_Ev,
    float* __restrict__ out)
{
    extern __shared__ float sm[];
    float* KVb0 = sm;              // 3 x [TJ][KP2] = 3 x 16640
    float* KVb1 = sm + 16640;
    float* KVb2 = sm + 33280;
    float* Qe   = sm + 49920;      // [8][DIM] = 1024
    float* wAs  = sm + 50944;      // [DIM] = 128
    float* pb0  = sm + 51072;      // [TJ][16] = 1024
    float* pb1  = sm + 52096;      // 1024
    float* l_ws = sm + 53120;      // [16][4] = 64
    // total 53184 floats = 212736 B

    const int tid  = threadIdx.x;
    const int lane = tid & 31;
    const int warp = tid >> 5;
    const int i0   = blockIdx.x * TI;
    // phase-e ids
    const int rh_e = warp >> 3;               // row half 0/1
    const int je   = (warp & 7) * 8 + (lane & 7);
    const int g    = lane >> 3;               // d-chunk / owned local row
    // accumulate ids
    const int dp   = tid & 63;                // d-pair
    const int jq   = (tid >> 6) & 3;          // j-quarter
    const int rh   = tid >> 8;                // row half 0/1

    // per-thread load slot base: idx = it*NT + tid; j = idx>>6 = it*8+(tid>>6),
    // c4 = tid&63 (NT multiple of 64) -> off = koff0 + it*8*KP2*4 bytes
    const unsigned koff0 = (unsigned)((((tid >> 6) * KP2) + (tid & 63) * 4) * 4);

    // init Q table (row-major, 8 rows) + wA
    for (int idx = tid; idx < TI * DIM; idx += NT) {
        const int r = idx >> 7, dd = idx & 127;
        Qe[idx] = g_Q[(i0 + r) * DIM + dd];
    }
    if (tid < DIM) wAs[tid] = wA[tid];

    // accumulate-phase Q d-pairs (rows rh*4..rh*4+3)
    const ull q0p = *(const ull*)&g_Q[(i0 + rh * 4 + 0) * DIM + 2 * dp];
    const ull q1p = *(const ull*)&g_Q[(i0 + rh * 4 + 1) * DIM + 2 * dp];
    const ull q2p = *(const ull*)&g_Q[(i0 + rh * 4 + 2) * DIM + 2 * dp];
    const ull q3p = *(const ull*)&g_Q[(i0 + rh * 4 + 3) * DIM + 2 * dp];

    ull af0 = 0ull, af1 = 0ull, af2 = 0ull, af3 = 0ull;
    ull av0 = 0ull, av1 = 0ull, av2 = 0ull, av3 = 0ull;
    float l_acc = 0.f;

    // rotating buffers: at top of iter ti, KVe=KV(ti), KVa=KV(ti-1), KVn=target
    float *KVe = KVb0, *KVa = KVb2, *KVn = KVb1;
    float *p_cur = pb0, *p_prev = pb1;

    // prologue: async-load KV(0) into buf0
    {
        const unsigned b = (unsigned)__cvta_generic_to_shared(KVb0);
        const float4* KVg = (const float4*)(g_KV);
#pragma unroll
        for (int it = 0; it < 8; it++)
            cpa16(b + koff0 + (unsigned)(it * 8 * KP2 * 4), &KVg[it * NT + tid]);
        CP_COMMIT();
    }

    for (int ti = 0; ti < NTILE; ti++) {
        CP_WAIT0();        // KV(ti) landed
        __syncthreads();   // p(ti-1) visible; buffers safe to rotate/overwrite

        // issue KV(ti+1) — overlaps whole merged phase
        if (ti + 1 < NTILE) {
            const unsigned b = (unsigned)__cvta_generic_to_shared(KVn);
            const float4* KVg = (const float4*)(g_KV + (ti + 1) * TJ * 256);
#pragma unroll
            for (int it = 0; it < 8; it++)
                cpa16(b + koff0 + (unsigned)(it * 8 * KP2 * 4), &KVg[it * NT + tid]);
            CP_COMMIT();
        }

        if (ti == 0) {
            // e-only
            ull e0 = 0ull, e1 = 0ull, e2 = 0ull, e3 = 0ull;
            const float* kpE = KVe + je * KP2;
            const float* QhE = Qe + rh_e * 4 * DIM;
#pragma unroll
            for (int it = 0; it < 8; it++) E_IT(it);
            E_FIN();
        } else {
            // merged: phase-e(ti) + accumulate(ti-1), interleaved
            ull e0 = 0ull, e1 = 0ull, e2 = 0ull, e3 = 0ull;
            const float* kpE = KVe + je * KP2;
            const float* QhE = Qe + rh_e * 4 * DIM;
            const float* kvpA = KVa + 4 * dp;
            const float* ppA = p_prev + 8 * rh;
#pragma unroll
            for (int u = 0; u < 16; u++) {
                ACC_J(u);
                if ((u & 1) == 0) E_IT(u >> 1);
            }
            E_FIN();
        }

        // rotate buffers
        float* t;
        t = KVa; KVa = KVe; KVe = KVn; KVn = t;
        t = p_prev; p_prev = p_cur; p_cur = t;
    }

    __syncthreads();       // p(15) visible
    {   // final accumulate(15): KVa=KV(15) (=KVb0), p_prev=p(15)
        const float* kvpA = KVa + 4 * dp;
        const float* ppA = p_prev + 8 * rh;
#pragma unroll 4
        for (int u = 0; u < 16; u++) ACC_J(u);
    }

    // ================= epilogue =================
    // reduce l_acc over the 8 je-lanes of each g-group
#pragma unroll
    for (int off = 1; off <= 4; off <<= 1)
        l_acc += __shfl_xor_sync(0xffffffffu, l_acc, off);
    if ((lane & 7) == 0) l_ws[warp * 4 + g] = l_acc;

    // exchange in KVb1 (final acc used KVb0): xch[rh][acc 0..7][jq][dp]
    ull* xch = (ull*)KVb1;
    {
        const int bse = ((rh * 8 + 0) * 4 + jq) * 64 + dp;
        xch[bse + 0 * 256] = af0;
        xch[bse + 1 * 256] = af1;
        xch[bse + 2 * 256] = af2;
        xch[bse + 3 * 256] = af3;
        xch[bse + 4 * 256] = av0;
        xch[bse + 5 * 256] = av1;
        xch[bse + 6 * 256] = av2;
        xch[bse + 7 * 256] = av3;
    }
    __syncthreads();

    // combine over jq, normalize; Rp[k][8] in KVb2, avs[8][128] in Qe
    float* Rp  = KVb2;
    float* avs = Qe;
    {
        const int d = tid & 127, rp = tid >> 7;      // rows 2rp, 2rp+1
        const int dpc = d >> 1, hc = d & 1;
        const float* xf = (const float*)xch;
#pragma unroll
        for (int rr = 0; rr < 2; rr++) {
            const int r = 2 * rp + rr;
            const int rhh = r >> 2, ra = r & 3;
            float lr = 0.f;
#pragma unroll
            for (int w = 0; w < 8; w++) lr += l_ws[(rhh * 8 + w) * 4 + ra];
            const float il = 1.f / lr;
            float af = 0.f, av = 0.f;
#pragma unroll
            for (int q = 0; q < 4; q++) {
                af += xf[(((rhh * 8 + ra    ) * 4 + q) * 64 + dpc) * 2 + hc];
                av += xf[(((rhh * 8 + 4 + ra) * 4 + q) * 64 + dpc) * 2 + hc];
            }
            Rp[d * 8 + r]    = af * il;
            avs[r * 128 + d] = av * il;
        }
    }
    __syncthreads();

    // GEMM: thread (d, s=tid>>7) computes rows 2s, 2s+1 over full k
    {
        const int d = tid & 127, s = tid >> 7;
        const float bv = b_Ev[d];
        float o0 = avs[(2 * s) * 128 + d] + bv;
        float o1 = avs[(2 * s + 1) * 128 + d] + bv;
#pragma unroll 4
        for (int k = 0; k < DIM; k++) {
            const float wv = W_Ev[k * DIM + d];
            const float2 r2 = *(const float2*)&Rp[k * 8 + 2 * s];  // broadcast
            o0 += r2.x * wv;
            o1 += r2.y * wv;
        }
        out[(i0 + 2 * s) * DIM + d]     = o0;
        out[(i0 + 2 * s + 1) * DIM + d] = o1;
    }
}

// ---------------------------------------------------------------------------
extern "C" void kernel_launch(void* const* d_in, const int* in_sizes, int n_in,
                              void* d_out, int out_size)
{
    const float* x    = (const float*)d_in[0];
    const float* W_Q  = (const float*)d_in[1];
    const float* b_Q  = (const float*)d_in[2];
    const float* W_K  = (const float*)d_in[3];
    const float* b_K  = (const float*)d_in[4];
    const float* W_V  = (const float*)d_in[5];
    const float* b_V  = (const float*)d_in[6];
    const float* W_Ev = (const float*)d_in[7];
    const float* b_Ev = (const float*)d_in[8];
    const float* W_A  = (const float*)d_in[9];
    // d_in[10] = b_A: cancels in softmax; sum(alpha)=1 handles b_Ev; unused.
    float* out = (float*)d_out;

    const int smem2 = 53184 * (int)sizeof(float);  // 212736 B -> 1 CTA/SM
    cudaFuncSetAttribute(attn_kernel, cudaFuncAttributeMaxDynamicSharedMemorySize, smem2);

    qkv_kernel<<<NTOK / 8, 384>>>(x, W_Q, b_Q, W_K, b_K, W_V, b_V);
    attn_kernel<<<NTOK / TI, NT, smem2>>>(W_A, W_Ev, b_Ev, out);
}